// round 9
// baseline (speedup 1.0000x reference)
#include <cuda_runtime.h>
#include <cstdint>

#define NN 8192
#define FF 8
#define GWARPS 4                     // gemv warps per block
#define TPB (GWARPS * 32 + 32)       // 160: 4 gemv warps + 1 fid warp
#define GT (GWARPS * 32)             // 128 gemv threads
#define GRPW 8                       // rows per gemv warp
#define RPB (GWARPS * GRPW)          // 32 rows per block
#define NB (NN / RPB)                // 256 blocks (homogeneous)
#define CH 128                       // j per chunk (lane owns 4 consecutive j)
#define NCH (NN / CH)                // 64 chunks
#define XT 1024                      // x tile nodes (8 chunks)
#define FTS 128                      // fid tile
#define FT (NN / FTS)                // 64
#define NPAIRS (FT * (FT + 1) / 2)   // 2080 tile pairs
#define RT9 0.94868329805051381f     // sqrt(0.9)

// dynamic smem: [0, 32768) gemv x tile, [32768, 36864) fid j-tile stage
#define SM_FID 32768
#define SMEM_DYN 36864

typedef unsigned long long ull;

__device__ float g_dense[NN * FF];

// ---------------- f32x2 helpers ----------------
__device__ __forceinline__ ull fma2(ull a, ull b, ull c) {
    ull d; asm("fma.rn.f32x2 %0, %1, %2, %3;" : "=l"(d) : "l"(a), "l"(b), "l"(c)); return d;
}
__device__ __forceinline__ ull mul2(ull a, ull b) {
    ull d; asm("mul.rn.f32x2 %0, %1, %2;" : "=l"(d) : "l"(a), "l"(b)); return d;
}
__device__ __forceinline__ ull add2(ull a, ull b) {
    ull d; asm("add.rn.f32x2 %0, %1, %2;" : "=l"(d) : "l"(a), "l"(b)); return d;
}
__device__ __forceinline__ ull pack2(float lo, float hi) {
    ull d; asm("mov.b64 %0, {%1, %2};" : "=l"(d) : "f"(lo), "f"(hi)); return d;
}
__device__ __forceinline__ void unpack2(ull v, float& lo, float& hi) {
    asm("mov.b64 {%0, %1}, %2;" : "=f"(lo), "=f"(hi) : "l"(v));
}
__device__ __forceinline__ float ftanh(float x) {
    float t = fabsf(x);
    float e = __expf(-2.0f * t);
    float r = __fdividef(1.0f - e, 1.0f + e);
    return copysignf(r, x);
}
__device__ __forceinline__ float fsigmoid(float x) {
    float e = __expf(-fabsf(x));
    float p = __fdividef(1.0f, 1.0f + e);
    return (x >= 0.0f) ? p : 1.0f - p;
}

// =================================================================
// Homogeneous mixed kernel, 256 identical blocks of 5 warps:
//   warps 0-3: dense gemv over this block's 32 rows of A
//   warp 4:    ~8 fid tile-pairs (grid-stride), hidden in gemv's
//              memory-stall issue slots on the same SM
// Both sides atomicAdd into g_dense (zeroed before launch).
// gemv warps sync via named barrier 1 (128 threads); fid warp
// never participates in block-wide barriers.
// =================================================================
__global__ void __launch_bounds__(TPB, 2)
mixed_kernel(const float* __restrict__ A, const float* __restrict__ X)
{
    extern __shared__ __align__(16) char sm[];
    const int tid  = threadIdx.x;
    const int lane = tid & 31;
    const int warp = tid >> 5;

    uint32_t smb;
    asm("{ .reg .u64 t; cvta.to.shared.u64 t, %1; cvt.u32.u64 %0, t; }"
        : "=r"(smb) : "l"(sm));

    if (warp < GWARPS) {
        // ===================== gemv =====================
        // smem x layout (position-permuted): node j in tile:
        // c=j>>7 (chunk), l=(j>>2)&31 (lane), r=j&3; feature pairs at
        // c*4096 + (2r+{0,1})*512 + l*16 (features 4-7 at +64B)
        const int i0 = blockIdx.x * RPB + warp * GRPW;

        ull acc[GRPW][4];
        #pragma unroll
        for (int r = 0; r < GRPW; r++)
            #pragma unroll
            for (int kk = 0; kk < 4; kk++) acc[r][kk] = 0ull;

        const float* Ab = A + (size_t)i0 * NN + lane * 4;
        float4 b0[GRPW], b1[GRPW];

        #define LDA(n, B)                                                      \
            do {                                                               \
                int n_ = (n); if (n_ >= NCH) n_ -= NCH;                        \
                const float* p_ = Ab + (size_t)n_ * CH;                        \
                _Pragma("unroll")                                              \
                for (int r_ = 0; r_ < GRPW; r_++)                              \
                    (B)[r_] = __ldcs(reinterpret_cast<const float4*>(p_ + (size_t)r_ * NN)); \
            } while (0)

        #define HALF(B, c0, c1, q0off)                                         \
            do {                                                                \
                ull pa0_, pa1_, pb0_, pb1_, pc0_, pc1_, pd0_, pd1_;             \
                asm("ld.shared.v2.b64 {%0, %1}, [%2];" : "=l"(pa0_), "=l"(pa1_) \
                    : "r"(ba_ + (q0off)));                                      \
                asm("ld.shared.v2.b64 {%0, %1}, [%2];" : "=l"(pb0_), "=l"(pb1_) \
                    : "r"(ba_ + (q0off) + 512));                                \
                asm("ld.shared.v2.b64 {%0, %1}, [%2];" : "=l"(pc0_), "=l"(pc1_) \
                    : "r"(ba_ + (q0off) + 1024));                               \
                asm("ld.shared.v2.b64 {%0, %1}, [%2];" : "=l"(pd0_), "=l"(pd1_) \
                    : "r"(ba_ + (q0off) + 1536));                               \
                _Pragma("unroll")                                               \
                for (int r_ = 0; r_ < GRPW; r_++) {                             \
                    ull w0_ = pack2((B)[r_].c0, (B)[r_].c0);                    \
                    acc[r_][0] = fma2(w0_, pa0_, acc[r_][0]);                   \
                    acc[r_][1] = fma2(w0_, pa1_, acc[r_][1]);                   \
                    acc[r_][2] = fma2(w0_, pb0_, acc[r_][2]);                   \
                    acc[r_][3] = fma2(w0_, pb1_, acc[r_][3]);                   \
                    ull w1_ = pack2((B)[r_].c1, (B)[r_].c1);                    \
                    acc[r_][0] = fma2(w1_, pc0_, acc[r_][0]);                   \
                    acc[r_][1] = fma2(w1_, pc1_, acc[r_][1]);                   \
                    acc[r_][2] = fma2(w1_, pd0_, acc[r_][2]);                   \
                    acc[r_][3] = fma2(w1_, pd1_, acc[r_][3]);                   \
                }                                                               \
            } while (0)

        #define COMPUTE(cl, B)                                                  \
            do {                                                                \
                const uint32_t ba_ = smb + (uint32_t)(cl) * 4096 + (uint32_t)lane * 16; \
                HALF(B, x, y, 0);                                               \
                HALF(B, z, w, 2048);                                            \
            } while (0)

        LDA(0, b0); LDA(1, b1);

        #pragma unroll 1
        for (int t = 0; t < NCH / 8; t++) {
            asm volatile("bar.sync 1, %0;" :: "n"(GT) : "memory"); // prev tile consumed
            const int t0 = t * XT;
            for (int j = tid; j < XT; j += GT) {
                const float4* xp = reinterpret_cast<const float4*>(X + (size_t)(t0 + j) * FF);
                float4 a = __ldg(xp), b = __ldg(xp + 1);
                const int cc = j >> 7, ll = (j >> 2) & 31, rr = j & 3;
                ull* dst = reinterpret_cast<ull*>(sm + cc * 4096 + (2 * rr) * 512 + ll * 16);
                dst[0]  = pack2(a.x, a.y);
                dst[1]  = pack2(a.z, a.w);
                dst[64] = pack2(b.x, b.y);
                dst[65] = pack2(b.z, b.w);
            }
            asm volatile("bar.sync 1, %0;" :: "n"(GT) : "memory"); // tile visible

            #pragma unroll 1
            for (int cc = 0; cc < 8; cc += 2) {
                const int n = t * 8 + cc;
                COMPUTE(cc,     b0); LDA(n + 2, b0);
                COMPUTE(cc + 1, b1); LDA(n + 3, b1);
            }
        }
        #undef LDA
        #undef HALF
        #undef COMPUTE

        // warp butterfly reduction
        #pragma unroll
        for (int r = 0; r < GRPW; r++)
            #pragma unroll
            for (int kk = 0; kk < 4; kk++) {
                ull v = acc[r][kk];
                #pragma unroll
                for (int o = 16; o; o >>= 1)
                    v = add2(v, __shfl_xor_sync(0xffffffffu, v, o));
                acc[r][kk] = v;
            }

        if (lane < GRPW) {
            const int row = i0 + lane;
            #pragma unroll
            for (int kk = 0; kk < 4; kk++) {
                float lo, hi;
                unpack2(acc[lane][kk], lo, hi);
                atomicAdd(&g_dense[(size_t)row * FF + 2 * kk],     lo);
                atomicAdd(&g_dense[(size_t)row * FF + 2 * kk + 1], hi);
            }
        }
    } else {
        // ===================== fid (warp 4) =====================
        // fid ⟺ |xn_i·xn_j| >= sqrt(0.9); a hit makes the effective
        // weight exactly 1: add (1-A)*x both directions.
        ull* pb = reinterpret_cast<ull*>(sm + SM_FID);
        const uint32_t pbb = smb + SM_FID;

        #pragma unroll 1
        for (int p = blockIdx.x; p < NPAIRS; p += NB) {
            int ti = 0, rem = p;
            while (rem >= FT - ti) { rem -= FT - ti; ti++; }
            const int tj = ti + rem;

            __syncwarp();   // previous pair's pb reads done

            // stage normalized j-tile into smem (32B per node)
            #pragma unroll
            for (int k = 0; k < 4; k++) {
                const int row = lane + 32 * k;
                const float4* xp = reinterpret_cast<const float4*>(X + (size_t)(tj * FTS + row) * FF);
                float4 a = __ldg(xp), c = __ldg(xp + 1);
                float ss = a.x*a.x + a.y*a.y + a.z*a.z + a.w*a.w
                         + c.x*c.x + c.y*c.y + c.z*c.z + c.w*c.w;
                float inv = 1.0f / (sqrtf(ss) + 1e-12f);
                pb[row*4 + 0] = pack2(a.x*inv, a.y*inv);
                pb[row*4 + 1] = pack2(a.z*inv, a.w*inv);
                pb[row*4 + 2] = pack2(c.x*inv, c.y*inv);
                pb[row*4 + 3] = pack2(c.z*inv, c.w*inv);
            }
            // own 4 i-rows normalized into registers
            ull xi[4][4];
            #pragma unroll
            for (int k = 0; k < 4; k++) {
                const int row = lane + 32 * k;
                const float4* xp = reinterpret_cast<const float4*>(X + (size_t)(ti * FTS + row) * FF);
                float4 a = __ldg(xp), c = __ldg(xp + 1);
                float ss = a.x*a.x + a.y*a.y + a.z*a.z + a.w*a.w
                         + c.x*c.x + c.y*c.y + c.z*c.z + c.w*c.w;
                float inv = 1.0f / (sqrtf(ss) + 1e-12f);
                xi[k][0] = pack2(a.x*inv, a.y*inv);
                xi[k][1] = pack2(a.z*inv, a.w*inv);
                xi[k][2] = pack2(c.x*inv, c.y*inv);
                xi[k][3] = pack2(c.z*inv, c.w*inv);
            }
            __syncwarp();

            #pragma unroll 2
            for (int j = 0; j < FTS; j++) {
                ull q0, q1, q2, q3;
                asm("ld.shared.v2.b64 {%0, %1}, [%2];" : "=l"(q0), "=l"(q1)
                    : "r"(pbb + (uint32_t)j * 32));
                asm("ld.shared.v2.b64 {%0, %1}, [%2];" : "=l"(q2), "=l"(q3)
                    : "r"(pbb + (uint32_t)j * 32 + 16));
                #pragma unroll
                for (int k = 0; k < 4; k++) {
                    ull d = mul2(xi[k][0], q0);
                    d = fma2(xi[k][1], q1, d);
                    d = fma2(xi[k][2], q2, d);
                    d = fma2(xi[k][3], q3, d);
                    float lo, hi; unpack2(d, lo, hi);
                    const float s = lo + hi;
                    const int gi = ti * FTS + lane + 32 * k;
                    const int gj = tj * FTS + j;
                    if (fabsf(s) >= RT9 && (ti != tj || gj > gi)) {  // rare (~1e-4)
                        const float aij = __ldg(A + (size_t)gi * NN + gj);
                        const float aji = __ldg(A + (size_t)gj * NN + gi);
                        const float* xjv = X + (size_t)gj * FF;
                        const float* xiv = X + (size_t)gi * FF;
                        #pragma unroll
                        for (int f = 0; f < FF; f++)
                            atomicAdd(&g_dense[(size_t)gi * FF + f], (1.0f - aij) * __ldg(xjv + f));
                        #pragma unroll
                        for (int f = 0; f < FF; f++)
                            atomicAdd(&g_dense[(size_t)gj * FF + f], (1.0f - aji) * __ldg(xiv + f));
                    }
                }
            }
        }
    }
}

// =================================================================
// MLP tail (weights staged in smem), 128 blocks x 64 threads
// =================================================================
#define NW_TOT 785
__global__ void __launch_bounds__(64)
mlp_kernel(const float* __restrict__ Wfm, const float* __restrict__ bfm,
           const float* __restrict__ Wc1, const float* __restrict__ bc1,
           const float* __restrict__ Wp1, const float* __restrict__ bp1,
           const float* __restrict__ Wc2, const float* __restrict__ bc2,
           const float* __restrict__ Wp2, const float* __restrict__ bp2,
           const float* __restrict__ Wc3, const float* __restrict__ bc3,
           const float* __restrict__ Wh,  const float* __restrict__ bh,
           float* __restrict__ out)
{
    __shared__ float w[NW_TOT];
    const int tid = threadIdx.x;

    struct Seg { const float* src; int off, n; };
    const Seg segs[14] = {
        {Wfm,   0, 128}, {bfm, 128, 16}, {Wc1, 144, 256}, {bc1, 400, 16},
        {Wp1, 416, 192}, {bp1, 608, 12}, {Wc2, 620,  96}, {bc2, 716,  8},
        {Wp2, 724,  32}, {bp2, 756,  4}, {Wc3, 760,  16}, {bc3, 776,  4},
        {Wh,  780,   4}, {bh,  784,  1}
    };
    #pragma unroll
    for (int s = 0; s < 14; s++)
        for (int k = tid; k < segs[s].n; k += 64)
            w[segs[s].off + k] = __ldg(segs[s].src + k);
    __syncthreads();

    const int i = blockIdx.x * 64 + tid;

    float v[16], h[16];
    #pragma unroll
    for (int k = 0; k < 8; k++) v[k] = g_dense[(size_t)i * FF + k];

    #define LAYER(IN, OUT, WOFF, BOFF, src, dst)                          \
        do {                                                              \
            _Pragma("unroll")                                             \
            for (int j_ = 0; j_ < (OUT); j_++) {                          \
                float s_ = w[(BOFF) + j_];                                \
                _Pragma("unroll")                                         \
                for (int k_ = 0; k_ < (IN); k_++)                         \
                    s_ = fmaf((src)[k_], w[(WOFF) + k_ * (OUT) + j_], s_);\
                (dst)[j_] = ftanh(s_);                                    \
            }                                                             \
        } while (0)

    LAYER(8, 16,   0, 128, v, h);
    LAYER(16, 16, 144, 400, h, v);
    LAYER(16, 12, 416, 608, v, h);
    LAYER(12, 8,  620, 716, h, v);
    LAYER(8, 4,   724, 756, v, h);
    LAYER(4, 4,   760, 776, h, v);
    #undef LAYER

    float z = w[784];
    #pragma unroll
    for (int k = 0; k < 4; k++)
        z = fmaf(v[k], w[780 + k], z);
    out[i] = fsigmoid(z);
}

extern "C" void kernel_launch(void* const* d_in, const int* in_sizes, int n_in,
                              void* d_out, int out_size)
{
    const float* A = (const float*)d_in[0];
    const float* X = (const float*)d_in[1];

    cudaFuncSetAttribute(mixed_kernel,
                         cudaFuncAttributeMaxDynamicSharedMemorySize, SMEM_DYN);

    void* gd = nullptr;
    cudaGetSymbolAddress(&gd, g_dense);
    cudaMemsetAsync(gd, 0, sizeof(float) * NN * FF, 0);

    mixed_kernel<<<NB, TPB, SMEM_DYN>>>(A, X);

    mlp_kernel<<<NN / 64, 64>>>(
        (const float*)d_in[2],  (const float*)d_in[3],
        (const float*)d_in[4],  (const float*)d_in[5],
        (const float*)d_in[6],  (const float*)d_in[7],
        (const float*)d_in[8],  (const float*)d_in[9],
        (const float*)d_in[10], (const float*)d_in[11],
        (const float*)d_in[12], (const float*)d_in[13],
        (const float*)d_in[14], (const float*)d_in[15],
        (float*)d_out);
}

// round 10
// speedup vs baseline: 1.6562x; 1.6562x over previous
#include <cuda_runtime.h>
#include <cstdint>

#define NN 8192
#define FF 8
#define TPB 224                     // 7 warps
#define GRPW 4                      // rows per warp (phase 1)
#define RPB 28                      // rows per block
#define NB ((NN + RPB - 1) / RPB)   // 293 blocks (2/SM, one wave)
#define CH 128                      // j per chunk (lane owns 4 consecutive j)
#define NCH (NN / CH)               // 64 chunks
#define XT 1024                     // x tile nodes (8 chunks)
#define FTS 128                     // fid tile
#define FT (NN / FTS)               // 64
#define NPAIRS (FT * (FT + 1) / 2)  // 2080 tile pairs
#define RT9 0.94868329805051381f    // sqrt(0.9)

typedef unsigned long long ull;

__device__ float g_dense[NN * FF];
__device__ int   g_ctr;

// ---------------- f32x2 helpers ----------------
__device__ __forceinline__ ull fma2(ull a, ull b, ull c) {
    ull d; asm("fma.rn.f32x2 %0, %1, %2, %3;" : "=l"(d) : "l"(a), "l"(b), "l"(c)); return d;
}
__device__ __forceinline__ ull mul2(ull a, ull b) {
    ull d; asm("mul.rn.f32x2 %0, %1, %2;" : "=l"(d) : "l"(a), "l"(b)); return d;
}
__device__ __forceinline__ ull add2(ull a, ull b) {
    ull d; asm("add.rn.f32x2 %0, %1, %2;" : "=l"(d) : "l"(a), "l"(b)); return d;
}
__device__ __forceinline__ ull pack2(float lo, float hi) {
    ull d; asm("mov.b64 %0, {%1, %2};" : "=l"(d) : "f"(lo), "f"(hi)); return d;
}
__device__ __forceinline__ void unpack2(ull v, float& lo, float& hi) {
    asm("mov.b64 {%0, %1}, %2;" : "=f"(lo), "=f"(hi) : "l"(v));
}
__device__ __forceinline__ float ftanh(float x) {
    float t = fabsf(x);
    float e = __expf(-2.0f * t);
    float r = __fdividef(1.0f - e, 1.0f + e);
    return copysignf(r, x);
}
__device__ __forceinline__ float fsigmoid(float x) {
    float e = __expf(-fabsf(x));
    float p = __fdividef(1.0f, 1.0f + e);
    return (x >= 0.0f) ? p : 1.0f - p;
}

// =================================================================
// Fused kernel, 293 homogeneous blocks:
//   Phase 1: this block's 28 rows of the dense gemv (A @ X),
//            atomicAdd into zeroed g_dense (exclusive rows).
//   Phase 2: pull fid tile-pairs from a global atomic counter
//            until exhausted (dynamic balance across blocks).
// =================================================================
__global__ void __launch_bounds__(TPB, 2)
fused_kernel(const float* __restrict__ A, const float* __restrict__ X)
{
    // phase 1: [0,32768) x feature planes; phase 2 reuses [0,8192) for
    // normalized fid tiles; s_pair for the work-counter broadcast.
    __shared__ __align__(16) char sm[32768];
    __shared__ int s_pair;

    const int tid  = threadIdx.x;
    const int lane = tid & 31;
    const int warp = tid >> 5;

    uint32_t smb;
    asm("{ .reg .u64 t; cvta.to.shared.u64 t, %1; cvt.u32.u64 %0, t; }"
        : "=r"(smb) : "l"(sm));

    // =================== Phase 1: gemv ===================
    {
        const int iw = blockIdx.x * RPB + warp * GRPW;   // may exceed NN-4 on last block
        // per-row pointers with clamped loads (duplicates never stored)
        const float* Ap[GRPW];
        #pragma unroll
        for (int r = 0; r < GRPW; r++) {
            int row = iw + r; if (row > NN - 1) row = NN - 1;
            Ap[r] = A + (size_t)row * NN + lane * 4;
        }

        ull acc[GRPW][4];
        #pragma unroll
        for (int r = 0; r < GRPW; r++)
            #pragma unroll
            for (int kk = 0; kk < 4; kk++) acc[r][kk] = 0ull;

        float4 b0[GRPW], b1[GRPW], b2[GRPW], b3[GRPW];

        #define LDA(n, B)                                                      \
            do {                                                               \
                int n_ = (n); if (n_ >= NCH) n_ -= NCH;                        \
                _Pragma("unroll")                                              \
                for (int r_ = 0; r_ < GRPW; r_++)                              \
                    (B)[r_] = __ldcs(reinterpret_cast<const float4*>(Ap[r_] + (size_t)n_ * CH)); \
            } while (0)

        #define HALF(B, c0, c1, q0off)                                         \
            do {                                                                \
                ull pa0_, pa1_, pb0_, pb1_, pc0_, pc1_, pd0_, pd1_;             \
                asm("ld.shared.v2.b64 {%0, %1}, [%2];" : "=l"(pa0_), "=l"(pa1_) \
                    : "r"(ba_ + (q0off)));                                      \
                asm("ld.shared.v2.b64 {%0, %1}, [%2];" : "=l"(pb0_), "=l"(pb1_) \
                    : "r"(ba_ + (q0off) + 512));                                \
                asm("ld.shared.v2.b64 {%0, %1}, [%2];" : "=l"(pc0_), "=l"(pc1_) \
                    : "r"(ba_ + (q0off) + 1024));                               \
                asm("ld.shared.v2.b64 {%0, %1}, [%2];" : "=l"(pd0_), "=l"(pd1_) \
                    : "r"(ba_ + (q0off) + 1536));                               \
                _Pragma("unroll")                                               \
                for (int r_ = 0; r_ < GRPW; r_++) {                             \
                    ull w0_ = pack2((B)[r_].c0, (B)[r_].c0);                    \
                    acc[r_][0] = fma2(w0_, pa0_, acc[r_][0]);                   \
                    acc[r_][1] = fma2(w0_, pa1_, acc[r_][1]);                   \
                    acc[r_][2] = fma2(w0_, pb0_, acc[r_][2]);                   \
                    acc[r_][3] = fma2(w0_, pb1_, acc[r_][3]);                   \
                    ull w1_ = pack2((B)[r_].c1, (B)[r_].c1);                    \
                    acc[r_][0] = fma2(w1_, pc0_, acc[r_][0]);                   \
                    acc[r_][1] = fma2(w1_, pc1_, acc[r_][1]);                   \
                    acc[r_][2] = fma2(w1_, pd0_, acc[r_][2]);                   \
                    acc[r_][3] = fma2(w1_, pd1_, acc[r_][3]);                   \
                }                                                               \
            } while (0)

        #define COMPUTE(cl, B)                                                  \
            do {                                                                \
                const uint32_t ba_ = smb + (uint32_t)(cl) * 4096 + (uint32_t)lane * 16; \
                HALF(B, x, y, 0);                                               \
                HALF(B, z, w, 2048);                                            \
            } while (0)

        LDA(0, b0); LDA(1, b1); LDA(2, b2); LDA(3, b3);

        #pragma unroll 1
        for (int t = 0; t < NCH / 8; t++) {
            __syncthreads();     // previous tile fully consumed
            const int t0 = t * XT;
            for (int j = tid; j < XT; j += TPB) {
                const float4* xp = reinterpret_cast<const float4*>(X + (size_t)(t0 + j) * FF);
                float4 a = __ldg(xp), b = __ldg(xp + 1);
                const int cc = j >> 7, ll = (j >> 2) & 31, rr = j & 3;
                ull* dst = reinterpret_cast<ull*>(sm + cc * 4096 + (2 * rr) * 512 + ll * 16);
                dst[0]  = pack2(a.x, a.y);
                dst[1]  = pack2(a.z, a.w);
                dst[64] = pack2(b.x, b.y);
                dst[65] = pack2(b.z, b.w);
            }
            __syncthreads();

            #pragma unroll 1
            for (int cc = 0; cc < 8; cc += 4) {
                const int n = t * 8 + cc;
                COMPUTE(cc,     b0); LDA(n + 4, b0);
                COMPUTE(cc + 1, b1); LDA(n + 5, b1);
                COMPUTE(cc + 2, b2); LDA(n + 6, b2);
                COMPUTE(cc + 3, b3); LDA(n + 7, b3);
            }
        }
        #undef LDA
        #undef HALF
        #undef COMPUTE

        // warp butterfly reduction
        #pragma unroll
        for (int r = 0; r < GRPW; r++)
            #pragma unroll
            for (int kk = 0; kk < 4; kk++) {
                ull v = acc[r][kk];
                #pragma unroll
                for (int o = 16; o; o >>= 1)
                    v = add2(v, __shfl_xor_sync(0xffffffffu, v, o));
                acc[r][kk] = v;
            }

        if (lane < GRPW && iw + lane < NN) {   // exclusive rows only
            const int row = iw + lane;
            #pragma unroll
            for (int kk = 0; kk < 4; kk++) {
                float lo, hi;
                unpack2(acc[lane][kk], lo, hi);
                atomicAdd(&g_dense[(size_t)row * FF + 2 * kk],     lo);
                atomicAdd(&g_dense[(size_t)row * FF + 2 * kk + 1], hi);
            }
        }
    }

    // =================== Phase 2: fid work-queue ===================
    // fid ⟺ |xn_i·xn_j| >= sqrt(0.9); a hit makes the effective weight
    // exactly 1: add (1-A)*x in both directions.
    // smem reuse: pi0 [0,2048) pi1 [2048,4096) pj0 [4096,6144) pj1 [6144,8192)
    {
        ull* pi0 = reinterpret_cast<ull*>(sm);
        ull* pi1 = reinterpret_cast<ull*>(sm + 2048);
        ull* pj0 = reinterpret_cast<ull*>(sm + 4096);
        ull* pj1 = reinterpret_cast<ull*>(sm + 6144);

        while (true) {
            __syncthreads();   // previous pair's tile reads done; s_pair reusable
            if (tid == 0) s_pair = atomicAdd(&g_ctr, 1);
            __syncthreads();
            const int p = s_pair;
            if (p >= NPAIRS) break;

            int ti = 0, rem = p;
            while (rem >= FT - ti) { rem -= FT - ti; ti++; }
            const int tj = ti + rem;

            // stage normalized tiles (threads 0-127, one node each side)
            if (tid < FTS) {
                {
                    const float4* xp = reinterpret_cast<const float4*>(X + (size_t)(ti * FTS + tid) * FF);
                    float4 a = __ldg(xp), c = __ldg(xp + 1);
                    float ss = a.x*a.x + a.y*a.y + a.z*a.z + a.w*a.w
                             + c.x*c.x + c.y*c.y + c.z*c.z + c.w*c.w;
                    float inv = 1.0f / (sqrtf(ss) + 1e-12f);
                    pi0[tid*2 + 0] = pack2(a.x*inv, a.y*inv);
                    pi0[tid*2 + 1] = pack2(a.z*inv, a.w*inv);
                    pi1[tid*2 + 0] = pack2(c.x*inv, c.y*inv);
                    pi1[tid*2 + 1] = pack2(c.z*inv, c.w*inv);
                }
                {
                    const float4* xp = reinterpret_cast<const float4*>(X + (size_t)(tj * FTS + tid) * FF);
                    float4 a = __ldg(xp), c = __ldg(xp + 1);
                    float ss = a.x*a.x + a.y*a.y + a.z*a.z + a.w*a.w
                             + c.x*c.x + c.y*c.y + c.z*c.z + c.w*c.w;
                    float inv = 1.0f / (sqrtf(ss) + 1e-12f);
                    pj0[tid*2 + 0] = pack2(a.x*inv, a.y*inv);
                    pj0[tid*2 + 1] = pack2(a.z*inv, a.w*inv);
                    pj1[tid*2 + 0] = pack2(c.x*inv, c.y*inv);
                    pj1[tid*2 + 1] = pack2(c.z*inv, c.w*inv);
                }
            }
            __syncthreads();

            // 16384 cells striped over 224 threads
            #pragma unroll 4
            for (int c = tid; c < FTS * FTS; c += TPB) {
                const int i = c >> 7;
                const int j = c & (FTS - 1);
                ull a0, a1, b0, b1, c0, c1, d0, d1;
                asm("ld.shared.v2.b64 {%0, %1}, [%2];" : "=l"(a0), "=l"(a1)
                    : "r"(smb + (uint32_t)i * 16));
                asm("ld.shared.v2.b64 {%0, %1}, [%2];" : "=l"(b0), "=l"(b1)
                    : "r"(smb + 2048u + (uint32_t)i * 16));
                asm("ld.shared.v2.b64 {%0, %1}, [%2];" : "=l"(c0), "=l"(c1)
                    : "r"(smb + 4096u + (uint32_t)j * 16));
                asm("ld.shared.v2.b64 {%0, %1}, [%2];" : "=l"(d0), "=l"(d1)
                    : "r"(smb + 6144u + (uint32_t)j * 16));
                ull d = mul2(a0, c0);
                d = fma2(a1, c1, d);
                d = fma2(b0, d0, d);
                d = fma2(b1, d1, d);
                float lo, hi; unpack2(d, lo, hi);
                const float s = lo + hi;
                if (fabsf(s) >= RT9 && (ti != tj || j > i)) {   // rare (~1e-4)
                    const int gi = ti * FTS + i;
                    const int gj = tj * FTS + j;
                    const float aij = __ldg(A + (size_t)gi * NN + gj);
                    const float aji = __ldg(A + (size_t)gj * NN + gi);
                    const float* xjv = X + (size_t)gj * FF;
                    const float* xiv = X + (size_t)gi * FF;
                    #pragma unroll
                    for (int f = 0; f < FF; f++)
                        atomicAdd(&g_dense[(size_t)gi * FF + f], (1.0f - aij) * __ldg(xjv + f));
                    #pragma unroll
                    for (int f = 0; f < FF; f++)
                        atomicAdd(&g_dense[(size_t)gj * FF + f], (1.0f - aji) * __ldg(xiv + f));
                }
            }
        }
    }
}

// =================================================================
// MLP tail (weights staged in smem), 32 blocks x 256 threads
// =================================================================
#define NW_TOT 785
__global__ void __launch_bounds__(256)
mlp_kernel(const float* __restrict__ Wfm, const float* __restrict__ bfm,
           const float* __restrict__ Wc1, const float* __restrict__ bc1,
           const float* __restrict__ Wp1, const float* __restrict__ bp1,
           const float* __restrict__ Wc2, const float* __restrict__ bc2,
           const float* __restrict__ Wp2, const float* __restrict__ bp2,
           const float* __restrict__ Wc3, const float* __restrict__ bc3,
           const float* __restrict__ Wh,  const float* __restrict__ bh,
           float* __restrict__ out)
{
    __shared__ float w[NW_TOT];
    const int tid = threadIdx.x;

    struct Seg { const float* src; int off, n; };
    const Seg segs[14] = {
        {Wfm,   0, 128}, {bfm, 128, 16}, {Wc1, 144, 256}, {bc1, 400, 16},
        {Wp1, 416, 192}, {bp1, 608, 12}, {Wc2, 620,  96}, {bc2, 716,  8},
        {Wp2, 724,  32}, {bp2, 756,  4}, {Wc3, 760,  16}, {bc3, 776,  4},
        {Wh,  780,   4}, {bh,  784,  1}
    };
    #pragma unroll
    for (int s = 0; s < 14; s++)
        for (int k = tid; k < segs[s].n; k += 256)
            w[segs[s].off + k] = __ldg(segs[s].src + k);
    __syncthreads();

    const int i = blockIdx.x * 256 + tid;

    float v[16], h[16];
    #pragma unroll
    for (int k = 0; k < 8; k++) v[k] = g_dense[(size_t)i * FF + k];

    #define LAYER(IN, OUT, WOFF, BOFF, src, dst)                          \
        do {                                                              \
            _Pragma("unroll")                                             \
            for (int j_ = 0; j_ < (OUT); j_++) {                          \
                float s_ = w[(BOFF) + j_];                                \
                _Pragma("unroll")                                         \
                for (int k_ = 0; k_ < (IN); k_++)                         \
                    s_ = fmaf((src)[k_], w[(WOFF) + k_ * (OUT) + j_], s_);\
                (dst)[j_] = ftanh(s_);                                    \
            }                                                             \
        } while (0)

    LAYER(8, 16,   0, 128, v, h);
    LAYER(16, 16, 144, 400, h, v);
    LAYER(16, 12, 416, 608, v, h);
    LAYER(12, 8,  620, 716, h, v);
    LAYER(8, 4,   724, 756, v, h);
    LAYER(4, 4,   760, 776, h, v);
    #undef LAYER

    float z = w[784];
    #pragma unroll
    for (int k = 0; k < 4; k++)
        z = fmaf(v[k], w[780 + k], z);
    out[i] = fsigmoid(z);
}

extern "C" void kernel_launch(void* const* d_in, const int* in_sizes, int n_in,
                              void* d_out, int out_size)
{
    const float* A = (const float*)d_in[0];
    const float* X = (const float*)d_in[1];

    void* gd = nullptr;
    cudaGetSymbolAddress(&gd, g_dense);
    cudaMemsetAsync(gd, 0, sizeof(float) * NN * FF, 0);
    void* gc = nullptr;
    cudaGetSymbolAddress(&gc, g_ctr);
    cudaMemsetAsync(gc, 0, sizeof(int), 0);

    fused_kernel<<<NB, TPB>>>(A, X);

    mlp_kernel<<<NN / 256, 256>>>(
        (const float*)d_in[2],  (const float*)d_in[3],
        (const float*)d_in[4],  (const float*)d_in[5],
        (const float*)d_in[6],  (const float*)d_in[7],
        (const float*)d_in[8],  (const float*)d_in[9],
        (const float*)d_in[10], (const float*)d_in[11],
        (const float*)d_in[12], (const float*)d_in[13],
        (const float*)d_in[14], (const float*)d_in[15],
        (float*)d_out);
}

// round 11
// speedup vs baseline: 2.0907x; 1.2623x over previous
#include <cuda_runtime.h>
#include <cstdint>

#define NN 8192
#define FF 8
#define TPB 224                     // 7 warps (gemv)
#define GRPW 4                      // rows per warp
#define RPB 28                      // rows per block
#define NB ((NN + RPB - 1) / RPB)   // 293 blocks
#define CH 128                      // j per chunk (lane owns 4 consecutive j)
#define NCH (NN / CH)               // 64 chunks
#define XTN 512                     // x nodes per tile (4 chunks)
#define NTILE (NN / XTN)            // 16 tiles
#define FTS 128                     // fid tile
#define FT (NN / FTS)               // 64
#define NPAIRS (FT * (FT + 1) / 2)  // 2080 tile pairs
#define RT9 0.94868329805051381f    // sqrt(0.9)

typedef unsigned long long ull;

__device__ float g_dense[NN * FF];

// ---------------- f32x2 helpers ----------------
__device__ __forceinline__ ull fma2(ull a, ull b, ull c) {
    ull d; asm("fma.rn.f32x2 %0, %1, %2, %3;" : "=l"(d) : "l"(a), "l"(b), "l"(c)); return d;
}
__device__ __forceinline__ ull mul2(ull a, ull b) {
    ull d; asm("mul.rn.f32x2 %0, %1, %2;" : "=l"(d) : "l"(a), "l"(b)); return d;
}
__device__ __forceinline__ ull add2(ull a, ull b) {
    ull d; asm("add.rn.f32x2 %0, %1, %2;" : "=l"(d) : "l"(a), "l"(b)); return d;
}
__device__ __forceinline__ ull pack2(float lo, float hi) {
    ull d; asm("mov.b64 %0, {%1, %2};" : "=l"(d) : "f"(lo), "f"(hi)); return d;
}
__device__ __forceinline__ void unpack2(ull v, float& lo, float& hi) {
    asm("mov.b64 {%0, %1}, %2;" : "=f"(lo), "=f"(hi) : "l"(v));
}
__device__ __forceinline__ float ftanh(float x) {
    float t = fabsf(x);
    float e = __expf(-2.0f * t);
    float r = __fdividef(1.0f - e, 1.0f + e);
    return copysignf(r, x);
}
__device__ __forceinline__ float fsigmoid(float x) {
    float e = __expf(-fabsf(x));
    float p = __fdividef(1.0f, 1.0f + e);
    return (x >= 0.0f) ? p : 1.0f - p;
}

// =================================================================
// Kernel 1: g_dense = A @ X  (direct stores, exclusive rows)
// x tiles double-buffered via cp.async: stage tile t+1 while
// computing tile t -> no serial reload bubble.
// smem x layout per tile (position-permuted): tile-local node j:
// c=j>>7, l=(j>>2)&31, r=j&3; 16B piece (half h) at
// c*4096 + ((r*2+h)*512) + l*16.
// =================================================================
__global__ void __launch_bounds__(TPB, 2)
gemv_kernel(const float* __restrict__ A, const float* __restrict__ X)
{
    __shared__ __align__(16) char sm[2 * 16384];

    const int tid  = threadIdx.x;
    const int lane = tid & 31;
    const int warp = tid >> 5;

    uint32_t smb;
    asm("{ .reg .u64 t; cvta.to.shared.u64 t, %1; cvt.u32.u64 %0, t; }"
        : "=r"(smb) : "l"(sm));

    const int i0w = blockIdx.x * RPB + warp * GRPW;
    // clamped per-row pointers (rows >= NN read row NN-1, never stored)
    const float* Ap[GRPW];
    #pragma unroll
    for (int r = 0; r < GRPW; r++) {
        int row = i0w + r; if (row > NN - 1) row = NN - 1;
        Ap[r] = A + (size_t)row * NN + lane * 4;
    }

    ull acc[GRPW][4];
    #pragma unroll
    for (int r = 0; r < GRPW; r++)
        #pragma unroll
        for (int kk = 0; kk < 4; kk++) acc[r][kk] = 0ull;

    float4 b0[GRPW], b1[GRPW], b2[GRPW], b3[GRPW];

    #define LDA(n, B)                                                          \
        do {                                                                   \
            const int n_ = (n) & (NCH - 1);                                    \
            _Pragma("unroll")                                                  \
            for (int r_ = 0; r_ < GRPW; r_++)                                  \
                (B)[r_] = __ldcs(reinterpret_cast<const float4*>(Ap[r_] + (size_t)n_ * CH)); \
        } while (0)

    // stage x tile tt into buffer at byte offset bo (cp.async, 16B pieces)
    #define STAGE(tt, bo)                                                      \
        do {                                                                   \
            for (int p_ = tid; p_ < XTN * 2; p_ += TPB) {                      \
                const int j_ = p_ >> 1, h_ = p_ & 1;                           \
                const float* src_ = X + ((size_t)(tt) * XTN + j_) * FF + h_ * 4; \
                const int c_ = j_ >> 7, l_ = (j_ >> 2) & 31, r_ = j_ & 3;      \
                const uint32_t dst_ = smb + (bo) + c_ * 4096                   \
                                    + (r_ * 2 + h_) * 512 + l_ * 16;           \
                asm volatile("cp.async.ca.shared.global [%0], [%1], 16;"       \
                             :: "r"(dst_), "l"(src_));                         \
            }                                                                  \
            asm volatile("cp.async.commit_group;" ::: "memory");               \
        } while (0)

    #define HALF(B, c0, c1, q0off)                                             \
        do {                                                                   \
            ull pa0_, pa1_, pb0_, pb1_, pc0_, pc1_, pd0_, pd1_;                \
            asm("ld.shared.v2.b64 {%0, %1}, [%2];" : "=l"(pa0_), "=l"(pa1_)    \
                : "r"(ba_ + (q0off)));                                         \
            asm("ld.shared.v2.b64 {%0, %1}, [%2];" : "=l"(pb0_), "=l"(pb1_)    \
                : "r"(ba_ + (q0off) + 512));                                   \
            asm("ld.shared.v2.b64 {%0, %1}, [%2];" : "=l"(pc0_), "=l"(pc1_)    \
                : "r"(ba_ + (q0off) + 1024));                                  \
            asm("ld.shared.v2.b64 {%0, %1}, [%2];" : "=l"(pd0_), "=l"(pd1_)    \
                : "r"(ba_ + (q0off) + 1536));                                  \
            _Pragma("unroll")                                                  \
            for (int r_ = 0; r_ < GRPW; r_++) {                                \
                ull w0_ = pack2((B)[r_].c0, (B)[r_].c0);                       \
                acc[r_][0] = fma2(w0_, pa0_, acc[r_][0]);                      \
                acc[r_][1] = fma2(w0_, pa1_, acc[r_][1]);                      \
                acc[r_][2] = fma2(w0_, pb0_, acc[r_][2]);                      \
                acc[r_][3] = fma2(w0_, pb1_, acc[r_][3]);                      \
                ull w1_ = pack2((B)[r_].c1, (B)[r_].c1);                       \
                acc[r_][0] = fma2(w1_, pc0_, acc[r_][0]);                      \
                acc[r_][1] = fma2(w1_, pc1_, acc[r_][1]);                      \
                acc[r_][2] = fma2(w1_, pd0_, acc[r_][2]);                      \
                acc[r_][3] = fma2(w1_, pd1_, acc[r_][3]);                      \
            }                                                                  \
        } while (0)

    #define COMPUTE(cbase, B)                                                  \
        do {                                                                   \
            const uint32_t ba_ = (cbase) + (uint32_t)lane * 16;                \
            HALF(B, x, y, 0);                                                  \
            HALF(B, z, w, 2048);                                               \
        } while (0)

    STAGE(0, 0);
    LDA(0, b0); LDA(1, b1); LDA(2, b2); LDA(3, b3);

    #pragma unroll 1
    for (int t = 0; t < NTILE; t++) {
        asm volatile("cp.async.wait_group 0;" ::: "memory");
        __syncthreads();   // tile t visible everywhere; all reads of t-1 done
        if (t + 1 < NTILE) STAGE(t + 1, ((t + 1) & 1) * 16384);

        const uint32_t tb = smb + (uint32_t)(t & 1) * 16384;
        const int n = t * 4;
        COMPUTE(tb,          b0); LDA(n + 4, b0);
        COMPUTE(tb + 4096,   b1); LDA(n + 5, b1);
        COMPUTE(tb + 8192,   b2); LDA(n + 6, b2);
        COMPUTE(tb + 12288,  b3); LDA(n + 7, b3);
    }
    #undef LDA
    #undef STAGE
    #undef HALF
    #undef COMPUTE

    // warp butterfly reduction
    #pragma unroll
    for (int r = 0; r < GRPW; r++)
        #pragma unroll
        for (int kk = 0; kk < 4; kk++) {
            ull v = acc[r][kk];
            #pragma unroll
            for (int o = 16; o; o >>= 1)
                v = add2(v, __shfl_xor_sync(0xffffffffu, v, o));
            acc[r][kk] = v;
        }

    if (lane < GRPW && i0w + lane < NN) {     // exclusive row: direct store
        float2* out = reinterpret_cast<float2*>(&g_dense[(size_t)(i0w + lane) * FF]);
        #pragma unroll
        for (int kk = 0; kk < 4; kk++) {
            float lo, hi;
            unpack2(acc[lane][kk], lo, hi);
            out[kk] = make_float2(lo, hi);
        }
    }
}

// =================================================================
// Kernel 2: sparse fidelity corrections, register-blocked 4x4.
// fid ⟺ |xn_i·xn_j| >= sqrt(0.9); hit -> weight becomes exactly 1:
// atomicAdd (1-A)*x in both directions (after gemv's direct store).
// One tile-pair per block (2080 blocks x 128 threads).
// =================================================================
__global__ void __launch_bounds__(128)
fid_kernel(const float* __restrict__ A, const float* __restrict__ X)
{
    // i-tile permuted for conflict-free per-lane reads; j-tile plain (broadcast)
    __shared__ __align__(16) ull smi[512];
    __shared__ __align__(16) ull smj[512];

    const int tid = threadIdx.x;

    int p = blockIdx.x, ti = 0, rem = p;
    while (rem >= FT - ti) { rem -= FT - ti; ti++; }
    const int tj = ti + rem;

    // stage both tiles normalized (thread t = node t of each tile)
    {
        const float4* xp = reinterpret_cast<const float4*>(X + (size_t)(ti * FTS + tid) * FF);
        float4 a = __ldg(xp), c = __ldg(xp + 1);
        float ss = a.x*a.x + a.y*a.y + a.z*a.z + a.w*a.w
                 + c.x*c.x + c.y*c.y + c.z*c.z + c.w*c.w;
        float inv = 1.0f / (sqrtf(ss) + 1e-12f);
        // node t: group g=t>>2, r=t&3; piece k=r*2+h at ull idx g*2 + k*64
        const int g = tid >> 2, r = tid & 3;
        smi[g*2 + (r*2+0)*64 + 0] = pack2(a.x*inv, a.y*inv);
        smi[g*2 + (r*2+0)*64 + 1] = pack2(a.z*inv, a.w*inv);
        smi[g*2 + (r*2+1)*64 + 0] = pack2(c.x*inv, c.y*inv);
        smi[g*2 + (r*2+1)*64 + 1] = pack2(c.z*inv, c.w*inv);
    }
    {
        const float4* xp = reinterpret_cast<const float4*>(X + (size_t)(tj * FTS + tid) * FF);
        float4 a = __ldg(xp), c = __ldg(xp + 1);
        float ss = a.x*a.x + a.y*a.y + a.z*a.z + a.w*a.w
                 + c.x*c.x + c.y*c.y + c.z*c.z + c.w*c.w;
        float inv = 1.0f / (sqrtf(ss) + 1e-12f);
        smj[tid*4 + 0] = pack2(a.x*inv, a.y*inv);
        smj[tid*4 + 1] = pack2(a.z*inv, a.w*inv);
        smj[tid*4 + 2] = pack2(c.x*inv, c.y*inv);
        smj[tid*4 + 3] = pack2(c.z*inv, c.w*inv);
    }
    __syncthreads();

    uint32_t sbi, sbj;
    asm("{ .reg .u64 t; cvta.to.shared.u64 t, %1; cvt.u32.u64 %0, t; }" : "=r"(sbi) : "l"(smi));
    asm("{ .reg .u64 t; cvta.to.shared.u64 t, %1; cvt.u32.u64 %0, t; }" : "=r"(sbj) : "l"(smj));

    // own 4 i-nodes into registers: i-group = tid&31 (conflict-free 16B lane stride)
    const int gi4 = tid & 31;
    ull xi[4][4];
    #pragma unroll
    for (int k = 0; k < 8; k++) {
        ull u0, u1;
        asm("ld.shared.v2.b64 {%0, %1}, [%2];" : "=l"(u0), "=l"(u1)
            : "r"(sbi + (uint32_t)gi4 * 16 + (uint32_t)k * 512));
        xi[k >> 1][2 * (k & 1) + 0] = u0;
        xi[k >> 1][2 * (k & 1) + 1] = u1;
    }

    #pragma unroll 1
    for (int pass = 0; pass < 8; pass++) {
        const int jg = pass * 4 + (tid >> 5);   // j-group (all lanes in warp same -> broadcast)
        ull xj[4][4];
        #pragma unroll
        for (int r = 0; r < 4; r++) {
            ull u0, u1, u2, u3;
            asm("ld.shared.v2.b64 {%0, %1}, [%2];" : "=l"(u0), "=l"(u1)
                : "r"(sbj + (uint32_t)(jg * 4 + r) * 32));
            asm("ld.shared.v2.b64 {%0, %1}, [%2];" : "=l"(u2), "=l"(u3)
                : "r"(sbj + (uint32_t)(jg * 4 + r) * 32 + 16));
            xj[r][0] = u0; xj[r][1] = u1; xj[r][2] = u2; xj[r][3] = u3;
        }
        #pragma unroll
        for (int r = 0; r < 4; r++) {
            #pragma unroll
            for (int q = 0; q < 4; q++) {
                ull d = mul2(xi[r][0], xj[q][0]);
                d = fma2(xi[r][1], xj[q][1], d);
                d = fma2(xi[r][2], xj[q][2], d);
                d = fma2(xi[r][3], xj[q][3], d);
                float lo, hi; unpack2(d, lo, hi);
                const float s = lo + hi;
                if (fabsf(s) >= RT9) {          // rare (~1e-4)
                    const int gi = ti * FTS + gi4 * 4 + r;
                    const int gj = tj * FTS + jg * 4 + q;
                    if (ti != tj || gj > gi) {
                        const float aij = __ldg(A + (size_t)gi * NN + gj);
                        const float aji = __ldg(A + (size_t)gj * NN + gi);
                        const float* xjv = X + (size_t)gj * FF;
                        const float* xiv = X + (size_t)gi * FF;
                        #pragma unroll
                        for (int f = 0; f < FF; f++)
                            atomicAdd(&g_dense[(size_t)gi * FF + f], (1.0f - aij) * __ldg(xjv + f));
                        #pragma unroll
                        for (int f = 0; f < FF; f++)
                            atomicAdd(&g_dense[(size_t)gj * FF + f], (1.0f - aji) * __ldg(xiv + f));
                    }
                }
            }
        }
    }
}

// =================================================================
// Kernel 3: per-row MLP + sigmoid head (weights staged in smem)
// =================================================================
#define NW_TOT 785
__global__ void __launch_bounds__(256)
mlp_kernel(const float* __restrict__ Wfm, const float* __restrict__ bfm,
           const float* __restrict__ Wc1, const float* __restrict__ bc1,
           const float* __restrict__ Wp1, const float* __restrict__ bp1,
           const float* __restrict__ Wc2, const float* __restrict__ bc2,
           const float* __restrict__ Wp2, const float* __restrict__ bp2,
           const float* __restrict__ Wc3, const float* __restrict__ bc3,
           const float* __restrict__ Wh,  const float* __restrict__ bh,
           float* __restrict__ out)
{
    __shared__ float w[NW_TOT];
    const int tid = threadIdx.x;

    struct Seg { const float* src; int off, n; };
    const Seg segs[14] = {
        {Wfm,   0, 128}, {bfm, 128, 16}, {Wc1, 144, 256}, {bc1, 400, 16},
        {Wp1, 416, 192}, {bp1, 608, 12}, {Wc2, 620,  96}, {bc2, 716,  8},
        {Wp2, 724,  32}, {bp2, 756,  4}, {Wc3, 760,  16}, {bc3, 776,  4},
        {Wh,  780,   4}, {bh,  784,  1}
    };
    #pragma unroll
    for (int s = 0; s < 14; s++)
        for (int k = tid; k < segs[s].n; k += 256)
            w[segs[s].off + k] = __ldg(segs[s].src + k);
    __syncthreads();

    const int i = blockIdx.x * 256 + tid;

    float v[16], h[16];
    #pragma unroll
    for (int k = 0; k < 8; k++) v[k] = g_dense[(size_t)i * FF + k];

    #define LAYER(IN, OUT, WOFF, BOFF, src, dst)                          \
        do {                                                              \
            _Pragma("unroll")                                             \
            for (int j_ = 0; j_ < (OUT); j_++) {                          \
                float s_ = w[(BOFF) + j_];                                \
                _Pragma("unroll")                                         \
                for (int k_ = 0; k_ < (IN); k_++)                         \
                    s_ = fmaf((src)[k_], w[(WOFF) + k_ * (OUT) + j_], s_);\
                (dst)[j_] = ftanh(s_);                                    \
            }                                                             \
        } while (0)

    LAYER(8, 16,   0, 128, v, h);
    LAYER(16, 16, 144, 400, h, v);
    LAYER(16, 12, 416, 608, v, h);
    LAYER(12, 8,  620, 716, h, v);
    LAYER(8, 4,   724, 756, v, h);
    LAYER(4, 4,   760, 776, h, v);
    #undef LAYER

    float z = w[784];
    #pragma unroll
    for (int k = 0; k < 4; k++)
        z = fmaf(v[k], w[780 + k], z);
    out[i] = fsigmoid(z);
}

extern "C" void kernel_launch(void* const* d_in, const int* in_sizes, int n_in,
                              void* d_out, int out_size)
{
    const float* A = (const float*)d_in[0];
    const float* X = (const float*)d_in[1];

    gemv_kernel<<<NB, TPB>>>(A, X);       // direct stores: no memset needed
    fid_kernel<<<NPAIRS, 128>>>(A, X);    // atomic corrections on top
    mlp_kernel<<<NN / 256, 256>>>(
        (const float*)d_in[2],  (const float*)d_in[3],
        (const float*)d_in[4],  (const float*)d_in[5],
        (const float*)d_in[6],  (const float*)d_in[7],
        (const float*)d_in[8],  (const float*)d_in[9],
        (const float*)d_in[10], (const float*)d_in[11],
        (const float*)d_in[12], (const float*)d_in[13],
        (const float*)d_in[14], (const float*)d_in[15],
        (float*)d_out);
}

// round 12
// speedup vs baseline: 2.1722x; 1.0390x over previous
#include <cuda_runtime.h>
#include <cstdint>

#define NN 8192
#define FF 8
#define TPB 224                     // 7 warps (gemv)
#define GRPW 8                      // rows per warp
#define RPB 56                      // rows per block
#define NB ((NN + RPB - 1) / RPB)   // 147 blocks (1/SM)
#define CH 128                      // j per chunk (lane owns 4 consecutive j)
#define NCH (NN / CH)               // 64 chunks
#define XTN 512                     // x nodes per tile (4 chunks)
#define NTILE (NN / XTN)            // 16 tiles
#define FTS 256                     // fid tile
#define FT (NN / FTS)               // 32
#define NPAIRS (FT * (FT + 1) / 2)  // 528 tile pairs
#define RT9 0.94868329805051381f    // sqrt(0.9)

typedef unsigned long long ull;

__device__ float g_dense[NN * FF];

// ---------------- f32x2 helpers ----------------
__device__ __forceinline__ ull fma2(ull a, ull b, ull c) {
    ull d; asm("fma.rn.f32x2 %0, %1, %2, %3;" : "=l"(d) : "l"(a), "l"(b), "l"(c)); return d;
}
__device__ __forceinline__ ull mul2(ull a, ull b) {
    ull d; asm("mul.rn.f32x2 %0, %1, %2;" : "=l"(d) : "l"(a), "l"(b)); return d;
}
__device__ __forceinline__ ull add2(ull a, ull b) {
    ull d; asm("add.rn.f32x2 %0, %1, %2;" : "=l"(d) : "l"(a), "l"(b)); return d;
}
__device__ __forceinline__ ull pack2(float lo, float hi) {
    ull d; asm("mov.b64 %0, {%1, %2};" : "=l"(d) : "f"(lo), "f"(hi)); return d;
}
__device__ __forceinline__ void unpack2(ull v, float& lo, float& hi) {
    asm("mov.b64 {%0, %1}, %2;" : "=f"(lo), "=f"(hi) : "l"(v));
}
__device__ __forceinline__ float ftanh(float x) {
    float t = fabsf(x);
    float e = __expf(-2.0f * t);
    float r = __fdividef(1.0f - e, 1.0f + e);
    return copysignf(r, x);
}
__device__ __forceinline__ float fsigmoid(float x) {
    float e = __expf(-fabsf(x));
    float p = __fdividef(1.0f, 1.0f + e);
    return (x >= 0.0f) ? p : 1.0f - p;
}

// =================================================================
// Kernel 1: g_dense = A @ X  (direct stores, exclusive rows)
// GRPW=8 rows/warp so the smem-x read traffic per A-byte halves
// (kernel was L1tex-bound at GRPW=4). x tiles double-buffered via
// cp.async. smem x layout per tile (position-permuted): tile-local
// node j: c=j>>7, l=(j>>2)&31, r=j&3; 16B piece (half h) at
// c*4096 + ((r*2+h)*512) + l*16.
// =================================================================
__global__ void __launch_bounds__(TPB, 1)
gemv_kernel(const float* __restrict__ A, const float* __restrict__ X)
{
    __shared__ __align__(16) char sm[2 * 16384];

    const int tid  = threadIdx.x;
    const int lane = tid & 31;
    const int warp = tid >> 5;

    uint32_t smb;
    asm("{ .reg .u64 t; cvta.to.shared.u64 t, %1; cvt.u32.u64 %0, t; }"
        : "=r"(smb) : "l"(sm));

    const int i0w = blockIdx.x * RPB + warp * GRPW;
    // clamped per-row pointers (rows >= NN read row NN-1, never stored)
    const float* Ap[GRPW];
    #pragma unroll
    for (int r = 0; r < GRPW; r++) {
        int row = i0w + r; if (row > NN - 1) row = NN - 1;
        Ap[r] = A + (size_t)row * NN + lane * 4;
    }

    ull acc[GRPW][4];
    #pragma unroll
    for (int r = 0; r < GRPW; r++)
        #pragma unroll
        for (int kk = 0; kk < 4; kk++) acc[r][kk] = 0ull;

    float4 b0[GRPW], b1[GRPW];

    #define LDA(n, B)                                                          \
        do {                                                                   \
            const int n_ = (n) & (NCH - 1);                                    \
            _Pragma("unroll")                                                  \
            for (int r_ = 0; r_ < GRPW; r_++)                                  \
                (B)[r_] = __ldcs(reinterpret_cast<const float4*>(Ap[r_] + (size_t)n_ * CH)); \
        } while (0)

    // stage x tile tt into buffer at byte offset bo (cp.async, 16B pieces)
    #define STAGE(tt, bo)                                                      \
        do {                                                                   \
            for (int p_ = tid; p_ < XTN * 2; p_ += TPB) {                      \
                const int j_ = p_ >> 1, h_ = p_ & 1;                           \
                const float* src_ = X + ((size_t)(tt) * XTN + j_) * FF + h_ * 4; \
                const int c_ = j_ >> 7, l_ = (j_ >> 2) & 31, r_ = j_ & 3;      \
                const uint32_t dst_ = smb + (bo) + c_ * 4096                   \
                                    + (r_ * 2 + h_) * 512 + l_ * 16;           \
                asm volatile("cp.async.ca.shared.global [%0], [%1], 16;"       \
                             :: "r"(dst_), "l"(src_));                         \
            }                                                                  \
            asm volatile("cp.async.commit_group;" ::: "memory");               \
        } while (0)

    #define HALF(B, c0, c1, q0off)                                             \
        do {                                                                   \
            ull pa0_, pa1_, pb0_, pb1_, pc0_, pc1_, pd0_, pd1_;                \
            asm("ld.shared.v2.b64 {%0, %1}, [%2];" : "=l"(pa0_), "=l"(pa1_)    \
                : "r"(ba_ + (q0off)));                                         \
            asm("ld.shared.v2.b64 {%0, %1}, [%2];" : "=l"(pb0_), "=l"(pb1_)    \
                : "r"(ba_ + (q0off) + 512));                                   \
            asm("ld.shared.v2.b64 {%0, %1}, [%2];" : "=l"(pc0_), "=l"(pc1_)    \
                : "r"(ba_ + (q0off) + 1024));                                  \
            asm("ld.shared.v2.b64 {%0, %1}, [%2];" : "=l"(pd0_), "=l"(pd1_)    \
                : "r"(ba_ + (q0off) + 1536));                                  \
            _Pragma("unroll")                                                  \
            for (int r_ = 0; r_ < GRPW; r_++) {                                \
                ull w0_ = pack2((B)[r_].c0, (B)[r_].c0);                       \
                acc[r_][0] = fma2(w0_, pa0_, acc[r_][0]);                      \
                acc[r_][1] = fma2(w0_, pa1_, acc[r_][1]);                      \
                acc[r_][2] = fma2(w0_, pb0_, acc[r_][2]);                      \
                acc[r_][3] = fma2(w0_, pb1_, acc[r_][3]);                      \
                ull w1_ = pack2((B)[r_].c1, (B)[r_].c1);                       \
                acc[r_][0] = fma2(w1_, pc0_, acc[r_][0]);                      \
                acc[r_][1] = fma2(w1_, pc1_, acc[r_][1]);                      \
                acc[r_][2] = fma2(w1_, pd0_, acc[r_][2]);                      \
                acc[r_][3] = fma2(w1_, pd1_, acc[r_][3]);                      \
            }                                                                  \
        } while (0)

    #define COMPUTE(cbase, B)                                                  \
        do {                                                                   \
            const uint32_t ba_ = (cbase) + (uint32_t)lane * 16;                \
            HALF(B, x, y, 0);                                                  \
            HALF(B, z, w, 2048);                                               \
        } while (0)

    STAGE(0, 0);
    LDA(0, b0); LDA(1, b1);

    #pragma unroll 1
    for (int t = 0; t < NTILE; t++) {
        asm volatile("cp.async.wait_group 0;" ::: "memory");
        __syncthreads();   // tile t visible; all reads of tile t-1 done
        if (t + 1 < NTILE) STAGE(t + 1, ((t + 1) & 1) * 16384);

        const uint32_t tb = smb + (uint32_t)(t & 1) * 16384;
        const int n = t * 4;
        COMPUTE(tb,          b0); LDA(n + 2, b0);
        COMPUTE(tb + 4096,   b1); LDA(n + 3, b1);
        COMPUTE(tb + 8192,   b0); LDA(n + 4, b0);
        COMPUTE(tb + 12288,  b1); LDA(n + 5, b1);
    }
    #undef LDA
    #undef STAGE
    #undef HALF
    #undef COMPUTE

    // warp butterfly reduction
    #pragma unroll
    for (int r = 0; r < GRPW; r++)
        #pragma unroll
        for (int kk = 0; kk < 4; kk++) {
            ull v = acc[r][kk];
            #pragma unroll
            for (int o = 16; o; o >>= 1)
                v = add2(v, __shfl_xor_sync(0xffffffffu, v, o));
            acc[r][kk] = v;
        }

    if (lane < GRPW && i0w + lane < NN) {     // exclusive row: direct store
        float2* out = reinterpret_cast<float2*>(&g_dense[(size_t)(i0w + lane) * FF]);
        #pragma unroll
        for (int kk = 0; kk < 4; kk++) {
            float lo, hi;
            unpack2(acc[lane][kk], lo, hi);
            out[kk] = make_float2(lo, hi);
        }
    }
}

// =================================================================
// Kernel 2: sparse fidelity corrections, register-blocked 4x4,
// 256-node tiles (528 blocks x 256 threads).
// fid ⟺ |xn_i·xn_j| >= sqrt(0.9); hit -> weight becomes exactly 1:
// atomicAdd (1-A)*x in both directions (after gemv's direct store).
// =================================================================
__global__ void __launch_bounds__(256)
fid_kernel(const float* __restrict__ A, const float* __restrict__ X)
{
    // i-tile permuted for conflict-free per-lane reads (8 k-planes of
    // 128 ull: node n -> group g=n>>2, r=n&3, piece k=r*2+h at
    // ull idx g*2 + k*128 + w); j-tile plain 32B/node (broadcast reads)
    __shared__ __align__(16) ull smi[1024];
    __shared__ __align__(16) ull smj[1024];

    const int tid = threadIdx.x;

    int p = blockIdx.x, ti = 0, rem = p;
    while (rem >= FT - ti) { rem -= FT - ti; ti++; }
    const int tj = ti + rem;

    // stage both tiles normalized (thread t = node t of each tile)
    {
        const float4* xp = reinterpret_cast<const float4*>(X + (size_t)(ti * FTS + tid) * FF);
        float4 a = __ldg(xp), c = __ldg(xp + 1);
        float ss = a.x*a.x + a.y*a.y + a.z*a.z + a.w*a.w
                 + c.x*c.x + c.y*c.y + c.z*c.z + c.w*c.w;
        float inv = 1.0f / (sqrtf(ss) + 1e-12f);
        const int g = tid >> 2, r = tid & 3;
        smi[g*2 + (r*2+0)*128 + 0] = pack2(a.x*inv, a.y*inv);
        smi[g*2 + (r*2+0)*128 + 1] = pack2(a.z*inv, a.w*inv);
        smi[g*2 + (r*2+1)*128 + 0] = pack2(c.x*inv, c.y*inv);
        smi[g*2 + (r*2+1)*128 + 1] = pack2(c.z*inv, c.w*inv);
    }
    {
        const float4* xp = reinterpret_cast<const float4*>(X + (size_t)(tj * FTS + tid) * FF);
        float4 a = __ldg(xp), c = __ldg(xp + 1);
        float ss = a.x*a.x + a.y*a.y + a.z*a.z + a.w*a.w
                 + c.x*c.x + c.y*c.y + c.z*c.z + c.w*c.w;
        float inv = 1.0f / (sqrtf(ss) + 1e-12f);
        smj[tid*4 + 0] = pack2(a.x*inv, a.y*inv);
        smj[tid*4 + 1] = pack2(a.z*inv, a.w*inv);
        smj[tid*4 + 2] = pack2(c.x*inv, c.y*inv);
        smj[tid*4 + 3] = pack2(c.z*inv, c.w*inv);
    }
    __syncthreads();

    uint32_t sbi, sbj;
    asm("{ .reg .u64 t; cvta.to.shared.u64 t, %1; cvt.u32.u64 %0, t; }" : "=r"(sbi) : "l"(smi));
    asm("{ .reg .u64 t; cvta.to.shared.u64 t, %1; cvt.u32.u64 %0, t; }" : "=r"(sbj) : "l"(smj));

    // own 4 i-nodes into registers: i-group = tid&63 (16B lane stride)
    const int gi4 = tid & 63;
    ull xi[4][4];
    #pragma unroll
    for (int k = 0; k < 8; k++) {
        ull u0, u1;
        asm("ld.shared.v2.b64 {%0, %1}, [%2];" : "=l"(u0), "=l"(u1)
            : "r"(sbi + (uint32_t)gi4 * 16 + (uint32_t)k * 1024));
        xi[k >> 1][2 * (k & 1) + 0] = u0;
        xi[k >> 1][2 * (k & 1) + 1] = u1;
    }

    const int jslot = tid >> 6;    // 0..3, constant within warp
    #pragma unroll 1
    for (int pass = 0; pass < 16; pass++) {
        const int jg = pass * 4 + jslot;    // j-group, warp-uniform -> broadcast LDS
        ull xj[4][4];
        #pragma unroll
        for (int r = 0; r < 4; r++) {
            ull u0, u1, u2, u3;
            asm("ld.shared.v2.b64 {%0, %1}, [%2];" : "=l"(u0), "=l"(u1)
                : "r"(sbj + (uint32_t)(jg * 4 + r) * 32));
            asm("ld.shared.v2.b64 {%0, %1}, [%2];" : "=l"(u2), "=l"(u3)
                : "r"(sbj + (uint32_t)(jg * 4 + r) * 32 + 16));
            xj[r][0] = u0; xj[r][1] = u1; xj[r][2] = u2; xj[r][3] = u3;
        }
        #pragma unroll
        for (int r = 0; r < 4; r++) {
            #pragma unroll
            for (int q = 0; q < 4; q++) {
                ull d = mul2(xi[r][0], xj[q][0]);
                d = fma2(xi[r][1], xj[q][1], d);
                d = fma2(xi[r][2], xj[q][2], d);
                d = fma2(xi[r][3], xj[q][3], d);
                float lo, hi; unpack2(d, lo, hi);
                const float s = lo + hi;
                if (fabsf(s) >= RT9) {          // rare (~1e-4)
                    const int gi = ti * FTS + gi4 * 4 + r;
                    const int gj = tj * FTS + jg * 4 + q;
                    if (ti != tj || gj > gi) {
                        const float aij = __ldg(A + (size_t)gi * NN + gj);
                        const float aji = __ldg(A + (size_t)gj * NN + gi);
                        const float* xjv = X + (size_t)gj * FF;
                        const float* xiv = X + (size_t)gi * FF;
                        #pragma unroll
                        for (int f = 0; f < FF; f++)
                            atomicAdd(&g_dense[(size_t)gi * FF + f], (1.0f - aij) * __ldg(xjv + f));
                        #pragma unroll
                        for (int f = 0; f < FF; f++)
                            atomicAdd(&g_dense[(size_t)gj * FF + f], (1.0f - aji) * __ldg(xiv + f));
                    }
                }
            }
        }
    }
}

// =================================================================
// Kernel 3: per-row MLP + sigmoid head (weights staged in smem)
// =================================================================
#define NW_TOT 785
__global__ void __launch_bounds__(256)
mlp_kernel(const float* __restrict__ Wfm, const float* __restrict__ bfm,
           const float* __restrict__ Wc1, const float* __restrict__ bc1,
           const float* __restrict__ Wp1, const float* __restrict__ bp1,
           const float* __restrict__ Wc2, const float* __restrict__ bc2,
           const float* __restrict__ Wp2, const float* __restrict__ bp2,
           const float* __restrict__ Wc3, const float* __restrict__ bc3,
           const float* __restrict__ Wh,  const float* __restrict__ bh,
           float* __restrict__ out)
{
    __shared__ float w[NW_TOT];
    const int tid = threadIdx.x;

    struct Seg { const float* src; int off, n; };
    const Seg segs[14] = {
        {Wfm,   0, 128}, {bfm, 128, 16}, {Wc1, 144, 256}, {bc1, 400, 16},
        {Wp1, 416, 192}, {bp1, 608, 12}, {Wc2, 620,  96}, {bc2, 716,  8},
        {Wp2, 724,  32}, {bp2, 756,  4}, {Wc3, 760,  16}, {bc3, 776,  4},
        {Wh,  780,   4}, {bh,  784,  1}
    };
    #pragma unroll
    for (int s = 0; s < 14; s++)
        for (int k = tid; k < segs[s].n; k += 256)
            w[segs[s].off + k] = __ldg(segs[s].src + k);
    __syncthreads();

    const int i = blockIdx.x * 256 + tid;

    float v[16], h[16];
    #pragma unroll
    for (int k = 0; k < 8; k++) v[k] = g_dense[(size_t)i * FF + k];

    #define LAYER(IN, OUT, WOFF, BOFF, src, dst)                          \
        do {                                                              \
            _Pragma("unroll")                                             \
            for (int j_ = 0; j_ < (OUT); j_++) {                          \
                float s_ = w[(BOFF) + j_];                                \
                _Pragma("unroll")                                         \
                for (int k_ = 0; k_ < (IN); k_++)                         \
                    s_ = fmaf((src)[k_], w[(WOFF) + k_ * (OUT) + j_], s_);\
                (dst)[j_] = ftanh(s_);                                    \
            }                                                             \
        } while (0)

    LAYER(8, 16,   0, 128, v, h);
    LAYER(16, 16, 144, 400, h, v);
    LAYER(16, 12, 416, 608, v, h);
    LAYER(12, 8,  620, 716, h, v);
    LAYER(8, 4,   724, 756, v, h);
    LAYER(4, 4,   760, 776, h, v);
    #undef LAYER

    float z = w[784];
    #pragma unroll
    for (int k = 0; k < 4; k++)
        z = fmaf(v[k], w[780 + k], z);
    out[i] = fsigmoid(z);
}

extern "C" void kernel_launch(void* const* d_in, const int* in_sizes, int n_in,
                              void* d_out, int out_size)
{
    const float* A = (const float*)d_in[0];
    const float* X = (const float*)d_in[1];

    gemv_kernel<<<NB, TPB>>>(A, X);       // direct stores: no memset needed
    fid_kernel<<<NPAIRS, 256>>>(A, X);    // atomic corrections on top
    mlp_kernel<<<NN / 256, 256>>>(
        (const float*)d_in[2],  (const float*)d_in[3],
        (const float*)d_in[4],  (const float*)d_in[5],
        (const float*)d_in[6],  (const float*)d_in[7],
        (const float*)d_in[8],  (const float*)d_in[9],
        (const float*)d_in[10], (const float*)d_in[11],
        (const float*)d_in[12], (const float*)d_in[13],
        (const float*)d_in[14], (const float*)d_in[15],
        (float*)d_out);
}